// round 13
// baseline (speedup 1.0000x reference)
#include <cuda_runtime.h>
#include <cuda_fp16.h>
#include <cstdint>

// Problem constants
#define BB 4
#define TT 2048
#define HH 1024
#define NH 16
#define HD 64
#define ROWS (BB*TT)          // 8192
#define QKV_COLS (3*HH)       // 3072

// Scratch (device globals; no runtime allocation allowed)
__device__ __half g_qkv_hi[(size_t)ROWS * QKV_COLS];
__device__ __half g_qkv_lo[(size_t)ROWS * QKV_COLS];
__device__ __half g_x_hi[(size_t)ROWS * HH];
__device__ __half g_x_lo[(size_t)ROWS * HH];
__device__ __half g_wqkv_hi[(size_t)QKV_COLS * HH];
__device__ __half g_wout_hi[(size_t)HH * HH];
__device__ __half g_attn_hi[(size_t)ROWS * HH];
__device__ __half g_attn_lo[(size_t)ROWS * HH];

// ---------------------------------------------------------------------------
// Helpers
// ---------------------------------------------------------------------------
__device__ __forceinline__ uint32_t smem_u32_of(const void* p) {
    uint32_t a;
    asm("{ .reg .u64 t; cvta.to.shared.u64 t, %1; cvt.u32.u64 %0, t; }"
        : "=r"(a) : "l"(p));
    return a;
}

#define CPA16(dst, src) \
    asm volatile("cp.async.cg.shared.global [%0], [%1], 16;" :: "r"(dst), "l"(src))
#define CPA_COMMIT() asm volatile("cp.async.commit_group;" ::: "memory")
#define CPA_WAIT1()  asm volatile("cp.async.wait_group 1;" ::: "memory")
#define CPA_WAIT0()  asm volatile("cp.async.wait_group 0;" ::: "memory")

__device__ __forceinline__ void ldsm4(uint32_t* r, uint32_t addr) {
    asm volatile("ldmatrix.sync.aligned.m8n8.x4.shared.b16 {%0,%1,%2,%3}, [%4];"
                 : "=r"(r[0]), "=r"(r[1]), "=r"(r[2]), "=r"(r[3]) : "r"(addr));
}
__device__ __forceinline__ void ldsm4t(uint32_t* r, uint32_t addr) {
    asm volatile("ldmatrix.sync.aligned.m8n8.x4.trans.shared.b16 {%0,%1,%2,%3}, [%4];"
                 : "=r"(r[0]), "=r"(r[1]), "=r"(r[2]), "=r"(r[3]) : "r"(addr));
}

__device__ __forceinline__ void mma_f16(float* c, const uint32_t* a, const uint32_t* b) {
    asm volatile(
        "mma.sync.aligned.m16n8k16.row.col.f32.f16.f16.f32 "
        "{%0,%1,%2,%3}, {%4,%5,%6,%7}, {%8,%9}, {%0,%1,%2,%3};"
        : "+f"(c[0]), "+f"(c[1]), "+f"(c[2]), "+f"(c[3])
        : "r"(a[0]), "r"(a[1]), "r"(a[2]), "r"(a[3]), "r"(b[0]), "r"(b[1]));
}

__device__ __forceinline__ float ex2f(float x) {
    float y;
    asm("ex2.approx.ftz.f32 %0, %1;" : "=f"(y) : "f"(x));
    return y;
}

__device__ __forceinline__ uint32_t pack2h(float a, float b) {
    __half2 v(__float2half(a), __float2half(b));
    return *(uint32_t*)&v;
}
__device__ __forceinline__ uint32_t pack2h_lo(float a, float b) {
    __half ha = __float2half(a), hb = __float2half(b);
    __half2 v(__float2half(a - __half2float(ha)),
              __float2half(b - __half2float(hb)));
    return *(uint32_t*)&v;
}

// ---------------------------------------------------------------------------
// fp32 -> fp16 hi/lo split, and hi-only convert (for weights)
// ---------------------------------------------------------------------------
__global__ __launch_bounds__(256) void split_f16(const float* __restrict__ src,
                                                 __half* __restrict__ hi,
                                                 __half* __restrict__ lo,
                                                 int n) {
    int i = (blockIdx.x * blockDim.x + threadIdx.x) * 4;
    if (i >= n) return;
    float4 v = *(const float4*)(src + i);
    *(uint32_t*)(hi + i)     = pack2h(v.x, v.y);
    *(uint32_t*)(hi + i + 2) = pack2h(v.z, v.w);
    *(uint32_t*)(lo + i)     = pack2h_lo(v.x, v.y);
    *(uint32_t*)(lo + i + 2) = pack2h_lo(v.z, v.w);
}

__global__ __launch_bounds__(256) void conv_f16(const float* __restrict__ src,
                                                __half* __restrict__ hi, int n) {
    int i = (blockIdx.x * blockDim.x + threadIdx.x) * 4;
    if (i >= n) return;
    float4 v = *(const float4*)(src + i);
    *(uint32_t*)(hi + i)     = pack2h(v.x, v.y);
    *(uint32_t*)(hi + i + 2) = pack2h(v.z, v.w);
}

// ---------------------------------------------------------------------------
// fp16x2 HMMA GEMM (NT): C = (Ahi+Alo) * Bhi^T, fp32 accum.
// Round-9 shape (256 thr, 2x4 warp grid, 64x32 warp tile) with MMA ordering
// split into hi-pass then lo-pass per k-step: same per-accumulator order
// (bit-identical results) but no back-to-back RAW on any accumulator.
// 3-stage swizzled pipeline, one __syncthreads per K-chunk.
// ---------------------------------------------------------------------------
#define KC 32
#define TILE2_B (128 * 64)          // 8192 B per tensor tile
#define STAGE2_B (3 * TILE2_B)      // 24576 B (Ah, Al, Bh)
#define GSMEM (3 * STAGE2_B)        // 73728 B, 3 stages

__device__ __forceinline__ uint32_t gsw(uint32_t row, uint32_t c4) {
    return row * 64u + ((c4 ^ (row & 3u)) << 4);
}

template <bool SPLIT>
__global__ __launch_bounds__(256) void gemm_hmma(
    const __half* __restrict__ Ahi, const __half* __restrict__ Alo,
    const __half* __restrict__ Bhi,
    float* __restrict__ C, __half* __restrict__ Chi,
    __half* __restrict__ Clo, int M, int N, int K) {
    extern __shared__ char sm[];
    const uint32_t sbase = smem_u32_of(sm);

    const int tid  = threadIdx.x;
    const int wid  = tid >> 5;
    const int lane = tid & 31;
    const int m0 = blockIdx.y * 128;
    const int n0 = blockIdx.x * 128;
    const int wm = wid >> 2;
    const int wn = wid & 3;

    // Loader: thread -> (row = tid>>1, two 16B chunks)
    const int lrow = tid >> 1;
    const int lc0  = (tid & 1) * 2;
    const __half* gAh = Ahi + (size_t)(m0 + lrow) * K;
    const __half* gAl = Alo + (size_t)(m0 + lrow) * K;
    const __half* gBh = Bhi + (size_t)(n0 + lrow) * K;

    float acc[4][4][4] = {};
    const int NCH = K / KC;

    auto load_stage = [&](int c, int s) {
        const uint32_t st = sbase + (uint32_t)s * STAGE2_B;
        #pragma unroll
        for (int j = 0; j < 2; j++) {
            const uint32_t c4 = (uint32_t)(lc0 + j);
            const uint32_t dof = gsw((uint32_t)lrow, c4);
            const size_t go = (size_t)c * KC + c4 * 8;
            CPA16(st + dof,               gAh + go);
            CPA16(st + TILE2_B + dof,     gAl + go);
            CPA16(st + 2 * TILE2_B + dof, gBh + go);
        }
    };

    load_stage(0, 0);
    CPA_COMMIT();
    load_stage(1, 1);
    CPA_COMMIT();

    const int arow = wm * 64 + (lane & 15);
    const uint32_t ac4b = (uint32_t)(lane >> 4);
    const int brow = wn * 32 + (lane & 7) + ((lane >> 4) << 3);
    const uint32_t bc4b = (uint32_t)((lane >> 3) & 1);

    for (int c = 0; c < NCH; c++) {
        if (c + 1 < NCH) CPA_WAIT1(); else CPA_WAIT0();
        __syncthreads();
        if (c + 2 < NCH) {
            load_stage(c + 2, (c + 2) % 3);
            CPA_COMMIT();
        }

        const uint32_t Ah_b = sbase + (uint32_t)(c % 3) * STAGE2_B;
        const uint32_t Al_b = Ah_b + TILE2_B;
        const uint32_t Bh_b = Ah_b + 2 * TILE2_B;

        #pragma unroll
        for (int ks = 0; ks < 2; ks++) {
            const uint32_t ac4 = (uint32_t)(ks * 2) + ac4b;
            const uint32_t bc4 = (uint32_t)(ks * 2) + bc4b;
            uint32_t bh[2][4];
            #pragma unroll
            for (int nj2 = 0; nj2 < 2; nj2++)
                ldsm4(bh[nj2], Bh_b + gsw((uint32_t)(brow + nj2 * 16), bc4));
            uint32_t ah[4][4], al[4][4];
            #pragma unroll
            for (int mi = 0; mi < 4; mi++) {
                const uint32_t aoff = gsw((uint32_t)(arow + mi * 16), ac4);
                ldsm4(ah[mi], Ah_b + aoff);
                ldsm4(al[mi], Al_b + aoff);
            }
            // hi pass: 16 MMAs, all-independent accumulators
            #pragma unroll
            for (int nj2 = 0; nj2 < 2; nj2++)
                #pragma unroll
                for (int mi = 0; mi < 4; mi++)
                    #pragma unroll
                    for (int j = 0; j < 2; j++)
                        mma_f16(acc[mi][nj2 * 2 + j], ah[mi], &bh[nj2][2 * j]);
            // lo pass: same per-accumulator order (hi before lo) -> bit-identical
            #pragma unroll
            for (int nj2 = 0; nj2 < 2; nj2++)
                #pragma unroll
                for (int mi = 0; mi < 4; mi++)
                    #pragma unroll
                    for (int j = 0; j < 2; j++)
                        mma_f16(acc[mi][nj2 * 2 + j], al[mi], &bh[nj2][2 * j]);
        }
    }

    const int gr = lane >> 2;
    const int gc = (lane & 3) * 2;
    #pragma unroll
    for (int mi = 0; mi < 4; mi++) {
        #pragma unroll
        for (int nj = 0; nj < 4; nj++) {
            const int row = m0 + wm * 64 + mi * 16 + gr;
            const int col = n0 + wn * 32 + nj * 8 + gc;
            if (SPLIT) {
                *(uint32_t*)&Chi[(size_t)row * N + col] = pack2h(acc[mi][nj][0], acc[mi][nj][1]);
                *(uint32_t*)&Clo[(size_t)row * N + col] = pack2h_lo(acc[mi][nj][0], acc[mi][nj][1]);
                *(uint32_t*)&Chi[(size_t)(row + 8) * N + col] = pack2h(acc[mi][nj][2], acc[mi][nj][3]);
                *(uint32_t*)&Clo[(size_t)(row + 8) * N + col] = pack2h_lo(acc[mi][nj][2], acc[mi][nj][3]);
            } else {
                *(float2*)&C[(size_t)row * N + col] =
                    make_float2(acc[mi][nj][0], acc[mi][nj][1]);
                *(float2*)&C[(size_t)(row + 8) * N + col] =
                    make_float2(acc[mi][nj][2], acc[mi][nj][3]);
            }
        }
    }
}

// ---------------------------------------------------------------------------
// Tensor-core causal flash attention (fp16x2). Unchanged from round 9.
// Q and P kept hi+lo (22-bit); K, V fp16-rounded. One CTA = 128-row q-tile,
// 8 warps, k-tiles of 64, double-buffered K/V, one __syncthreads per tile.
// ---------------------------------------------------------------------------
#define FA_STR 144                  // bytes per smem row (64 fp16 + 8 pad)
#define FA_QT  (128 * FA_STR)       // 18432 (Q tile: 128 rows)
#define FA_KT  (64 * FA_STR)        // 9216  (K/V tile: 64 rows)
#define FA_SMEM (2 * FA_QT + 2 * 2 * FA_KT)   // 73728

__global__ __launch_bounds__(256) void flash_tc(
    const __half* __restrict__ qkh, const __half* __restrict__ qkl,
    __half* __restrict__ oh, __half* __restrict__ ol) {
    extern __shared__ char sm[];
    const uint32_t sb = smem_u32_of(sm);
    const int qt = (int)gridDim.x - 1 - (int)blockIdx.x;   // long tiles first
    const int h  = blockIdx.y;
    const int b  = blockIdx.z;
    const int tid = threadIdx.x;
    const int w = tid >> 5;
    const int l = tid & 31;

    // Q load: 128 rows (hi + lo), thread -> (row = tid>>1, 64B half)
    {
        const int r  = tid >> 1;
        const int hf = tid & 1;
        const size_t qoff = ((size_t)(b * TT + qt * 128 + r)) * QKV_COLS + h * HD + hf * 32;
        const uint32_t d0 = sb + (uint32_t)r * FA_STR + (uint32_t)hf * 64;
        #pragma unroll
        for (int i = 0; i < 4; i++) {
            CPA16(d0 + 16 * i,         qkh + qoff + 8 * i);
            CPA16(d0 + FA_QT + 16 * i, qkl + qoff + 8 * i);
        }
    }

    // K/V load (hi only): 64 rows, thread -> (row = tid>>2, 32B quarter)
    const int kr = tid >> 2;
    const int kq = tid & 3;
    auto load_kv = [&](int kt, int s) {
        const size_t koff = ((size_t)(b * TT + kt * 64 + kr)) * QKV_COLS + HH + h * HD + kq * 16;
        const size_t voff = koff + HH;
        const uint32_t d = sb + 2 * FA_QT + (uint32_t)s * 2 * FA_KT
                         + (uint32_t)kr * FA_STR + (uint32_t)kq * 32;
        CPA16(d,              qkh + koff);
        CPA16(d + 16,         qkh + koff + 8);
        CPA16(d + FA_KT,      qkh + voff);
        CPA16(d + FA_KT + 16, qkh + voff + 8);
    };

    load_kv(0, 0);
    CPA_COMMIT();

    float o[8][4] = {};
    float m0 = -1e30f, m1 = -1e30f, l0 = 0.0f, l1 = 0.0f;
    uint32_t qfh[4][4], qfl[4][4];
    const int nkt = 2 * qt + 2;
    const float SCL = 0.18033688011112042f;    // (1/8) * log2(e)

    const uint32_t qa = sb + (uint32_t)(w * 16 + (l & 15)) * FA_STR + (uint32_t)((l >> 4) * 8) * 2;
    const uint32_t kb_row = (uint32_t)((l & 7) + ((l >> 4) << 3)) * FA_STR
                          + (uint32_t)(((l >> 3) & 1) * 8) * 2;
    const uint32_t vb_row = (uint32_t)((l & 7) + (((l >> 3) & 1) << 3)) * FA_STR
                          + (uint32_t)((l >> 4) * 8) * 2;

    const int grow0 = qt * 128 + w * 16 + (l >> 2);   // global q row (first)
    const int cb    = (l & 3) * 2;

    for (int kt = 0; kt < nkt; kt++) {
        const int s = kt & 1;
        CPA_WAIT0();
        __syncthreads();
        if (kt + 1 < nkt) {
            load_kv(kt + 1, s ^ 1);
            CPA_COMMIT();
        }

        if (kt == 0) {
            #pragma unroll
            for (int ks = 0; ks < 4; ks++) {
                ldsm4(qfh[ks], qa + ks * 32);
                ldsm4(qfl[ks], qa + FA_QT + ks * 32);
            }
        }

        const uint32_t Kb = sb + 2 * FA_QT + (uint32_t)s * 2 * FA_KT;
        const uint32_t Vb = Kb + FA_KT;

        // S = (Qhi+Qlo) Kh^T (fp16x2)
        float sc[8][4] = {};
        #pragma unroll
        for (int g = 0; g < 4; g++) {
            #pragma unroll
            for (int ks = 0; ks < 4; ks++) {
                uint32_t bh[4];
                ldsm4(bh, Kb + (uint32_t)(g * 16) * FA_STR + kb_row + ks * 32);
                mma_f16(sc[2 * g],     qfh[ks], &bh[0]);
                mma_f16(sc[2 * g],     qfl[ks], &bh[0]);
                mma_f16(sc[2 * g + 1], qfh[ks], &bh[2]);
                mma_f16(sc[2 * g + 1], qfl[ks], &bh[2]);
            }
        }

        // scale + causal mask (tiles at/after the diagonal band)
        const bool diag = (kt >= 2 * qt);
        float mx0 = -1e30f, mx1 = -1e30f;
        #pragma unroll
        for (int j = 0; j < 8; j++) {
            float s0 = sc[j][0] * SCL, s1 = sc[j][1] * SCL;
            float s2 = sc[j][2] * SCL, s3 = sc[j][3] * SCL;
            if (diag) {
                const int c = kt * 64 + j * 8 + cb;
                if (c     > grow0)     s0 = -1e30f;
                if (c + 1 > grow0)     s1 = -1e30f;
                if (c     > grow0 + 8) s2 = -1e30f;
                if (c + 1 > grow0 + 8) s3 = -1e30f;
            }
            sc[j][0] = s0; sc[j][1] = s1; sc[j][2] = s2; sc[j][3] = s3;
            mx0 = fmaxf(mx0, fmaxf(s0, s1));
            mx1 = fmaxf(mx1, fmaxf(s2, s3));
        }
        mx0 = fmaxf(mx0, __shfl_xor_sync(0xffffffffu, mx0, 1));
        mx0 = fmaxf(mx0, __shfl_xor_sync(0xffffffffu, mx0, 2));
        mx1 = fmaxf(mx1, __shfl_xor_sync(0xffffffffu, mx1, 1));
        mx1 = fmaxf(mx1, __shfl_xor_sync(0xffffffffu, mx1, 2));

        const float mn0 = fmaxf(m0, mx0);
        const float mn1 = fmaxf(m1, mx1);
        const float corr0 = ex2f(m0 - mn0);
        const float corr1 = ex2f(m1 - mn1);
        float sum0 = 0.0f, sum1 = 0.0f;
        #pragma unroll
        for (int j = 0; j < 8; j++) {
            sc[j][0] = ex2f(sc[j][0] - mn0); sum0 += sc[j][0];
            sc[j][1] = ex2f(sc[j][1] - mn0); sum0 += sc[j][1];
            sc[j][2] = ex2f(sc[j][2] - mn1); sum1 += sc[j][2];
            sc[j][3] = ex2f(sc[j][3] - mn1); sum1 += sc[j][3];
        }
        sum0 += __shfl_xor_sync(0xffffffffu, sum0, 1);
        sum0 += __shfl_xor_sync(0xffffffffu, sum0, 2);
        sum1 += __shfl_xor_sync(0xffffffffu, sum1, 1);
        sum1 += __shfl_xor_sync(0xffffffffu, sum1, 2);
        l0 = l0 * corr0 + sum0;
        l1 = l1 * corr1 + sum1;
        m0 = mn0; m1 = mn1;

        #pragma unroll
        for (int j = 0; j < 8; j++) {
            o[j][0] *= corr0; o[j][1] *= corr0;
            o[j][2] *= corr1; o[j][3] *= corr1;
        }

        // P fragments (hi/lo fp16) from S accumulators
        uint32_t pah[4][4], pal[4][4];
        #pragma unroll
        for (int ks = 0; ks < 4; ks++) {
            pah[ks][0] = pack2h(sc[2 * ks][0],        sc[2 * ks][1]);
            pal[ks][0] = pack2h_lo(sc[2 * ks][0],     sc[2 * ks][1]);
            pah[ks][1] = pack2h(sc[2 * ks][2],        sc[2 * ks][3]);
            pal[ks][1] = pack2h_lo(sc[2 * ks][2],     sc[2 * ks][3]);
            pah[ks][2] = pack2h(sc[2 * ks + 1][0],    sc[2 * ks + 1][1]);
            pal[ks][2] = pack2h_lo(sc[2 * ks + 1][0], sc[2 * ks + 1][1]);
            pah[ks][3] = pack2h(sc[2 * ks + 1][2],    sc[2 * ks + 1][3]);
            pal[ks][3] = pack2h_lo(sc[2 * ks + 1][2], sc[2 * ks + 1][3]);
        }

        // O += (Phi+Plo) Vh (fp16x2), V via ldmatrix.trans
        #pragma unroll
        for (int g = 0; g < 4; g++) {
            #pragma unroll
            for (int ks = 0; ks < 4; ks++) {
                uint32_t vh[4];
                ldsm4t(vh, Vb + (uint32_t)(ks * 16) * FA_STR + vb_row + g * 32);
                mma_f16(o[2 * g],     pah[ks], &vh[0]);
                mma_f16(o[2 * g],     pal[ks], &vh[0]);
                mma_f16(o[2 * g + 1], pah[ks], &vh[2]);
                mma_f16(o[2 * g + 1], pal[ks], &vh[2]);
            }
        }
    }

    // Epilogue: normalize + write hi/lo fp16
    const float i0 = 1.0f / l0;
    const float i1 = 1.0f / l1;
    const size_t row0 = (size_t)(b * TT + qt * 128 + w * 16 + (l >> 2));
    const size_t row1 = row0 + 8;
    const int colb = h * HD + cb;
    #pragma unroll
    for (int j = 0; j < 8; j++) {
        const size_t c = colb + j * 8;
        const float v0 = o[j][0] * i0, v1 = o[j][1] * i0;
        const float v2 = o[j][2] * i1, v3 = o[j][3] * i1;
        *(uint32_t*)&oh[row0 * HH + c] = pack2h(v0, v1);
        *(uint32_t*)&ol[row0 * HH + c] = pack2h_lo(v0, v1);
        *(uint32_t*)&oh[row1 * HH + c] = pack2h(v2, v3);
        *(uint32_t*)&ol[row1 * HH + c] = pack2h_lo(v2, v3);
    }
}

// ---------------------------------------------------------------------------
extern "C" void kernel_launch(void* const* d_in, const int* in_sizes, int n_in,
                              void* d_out, int out_size) {
    const float* x    = (const float*)d_in[0];   // [4,2048,1024]
    const float* Wqkv = (const float*)d_in[1];   // [3072,1024]
    const float* Wout = (const float*)d_in[2];   // [1024,1024]
    float* out = (float*)d_out;                  // [4,2048,1024]

    __half *qh, *ql, *xhi, *xlo, *wqh, *woh, *ahi, *alo;
    cudaGetSymbolAddress((void**)&qh,  g_qkv_hi);
    cudaGetSymbolAddress((void**)&ql,  g_qkv_lo);
    cudaGetSymbolAddress((void**)&xhi, g_x_hi);
    cudaGetSymbolAddress((void**)&xlo, g_x_lo);
    cudaGetSymbolAddress((void**)&wqh, g_wqkv_hi);
    cudaGetSymbolAddress((void**)&woh, g_wout_hi);
    cudaGetSymbolAddress((void**)&ahi, g_attn_hi);
    cudaGetSymbolAddress((void**)&alo, g_attn_lo);

    cudaFuncSetAttribute(gemm_hmma<true>,  cudaFuncAttributeMaxDynamicSharedMemorySize, GSMEM);
    cudaFuncSetAttribute(gemm_hmma<false>, cudaFuncAttributeMaxDynamicSharedMemorySize, GSMEM);
    cudaFuncSetAttribute(flash_tc, cudaFuncAttributeMaxDynamicSharedMemorySize, FA_SMEM);

    // Splits/converts
    {
        int n1 = ROWS * HH;
        split_f16<<<(n1 / 4 + 255) / 256, 256>>>(x, xhi, xlo, n1);
        int n2 = QKV_COLS * HH;
        conv_f16<<<(n2 / 4 + 255) / 256, 256>>>(Wqkv, wqh, n2);
        int n3 = HH * HH;
        conv_f16<<<(n3 / 4 + 255) / 256, 256>>>(Wout, woh, n3);
    }

    // 1) qkv = x @ W_qkv^T -> fp16 hi/lo directly
    gemm_hmma<true><<<dim3(QKV_COLS / 128, ROWS / 128), 256, GSMEM>>>(
        xhi, xlo, wqh, nullptr, qh, ql, ROWS, QKV_COLS, HH);

    // 2) tensor-core causal flash attention (128-row q-tiles) -> fp16 hi/lo
    flash_tc<<<dim3(TT / 128, NH, BB), 256, FA_SMEM>>>(qh, ql, ahi, alo);

    // 3) out = attn @ W_out^T -> fp32
    gemm_hmma<false><<<dim3(HH / 128, ROWS / 128), 256, GSMEM>>>(
        ahi, alo, woh, out, nullptr, nullptr, ROWS, HH, HH);
}

// round 16
// speedup vs baseline: 1.5993x; 1.5993x over previous
#include <cuda_runtime.h>
#include <cuda_fp16.h>
#include <cstdint>

// Problem constants
#define BB 4
#define TT 2048
#define HH 1024
#define NH 16
#define HD 64
#define ROWS (BB*TT)          // 8192
#define QKV_COLS (3*HH)       // 3072

// Scratch (device globals; no runtime allocation allowed)
__device__ __half g_qkv_hi[(size_t)ROWS * QKV_COLS];
__device__ __half g_qkv_lo[(size_t)ROWS * QKV_COLS];
__device__ __half g_x_hi[(size_t)ROWS * HH];
__device__ __half g_x_lo[(size_t)ROWS * HH];
__device__ __half g_wqkv_hi[(size_t)QKV_COLS * HH];
__device__ __half g_wout_hi[(size_t)HH * HH];
__device__ __half g_attn_hi[(size_t)ROWS * HH];
__device__ __half g_attn_lo[(size_t)ROWS * HH];

// ---------------------------------------------------------------------------
// Helpers
// ---------------------------------------------------------------------------
__device__ __forceinline__ uint32_t smem_u32_of(const void* p) {
    uint32_t a;
    asm("{ .reg .u64 t; cvta.to.shared.u64 t, %1; cvt.u32.u64 %0, t; }"
        : "=r"(a) : "l"(p));
    return a;
}

#define CPA16(dst, src) \
    asm volatile("cp.async.cg.shared.global [%0], [%1], 16;" :: "r"(dst), "l"(src))
#define CPA_COMMIT() asm volatile("cp.async.commit_group;" ::: "memory")
#define CPA_WAIT1()  asm volatile("cp.async.wait_group 1;" ::: "memory")
#define CPA_WAIT0()  asm volatile("cp.async.wait_group 0;" ::: "memory")

__device__ __forceinline__ void ldsm4(uint32_t* r, uint32_t addr) {
    asm volatile("ldmatrix.sync.aligned.m8n8.x4.shared.b16 {%0,%1,%2,%3}, [%4];"
                 : "=r"(r[0]), "=r"(r[1]), "=r"(r[2]), "=r"(r[3]) : "r"(addr));
}
__device__ __forceinline__ void ldsm4t(uint32_t* r, uint32_t addr) {
    asm volatile("ldmatrix.sync.aligned.m8n8.x4.trans.shared.b16 {%0,%1,%2,%3}, [%4];"
                 : "=r"(r[0]), "=r"(r[1]), "=r"(r[2]), "=r"(r[3]) : "r"(addr));
}

__device__ __forceinline__ void mma_f16(float* c, const uint32_t* a, const uint32_t* b) {
    asm volatile(
        "mma.sync.aligned.m16n8k16.row.col.f32.f16.f16.f32 "
        "{%0,%1,%2,%3}, {%4,%5,%6,%7}, {%8,%9}, {%0,%1,%2,%3};"
        : "+f"(c[0]), "+f"(c[1]), "+f"(c[2]), "+f"(c[3])
        : "r"(a[0]), "r"(a[1]), "r"(a[2]), "r"(a[3]), "r"(b[0]), "r"(b[1]));
}

__device__ __forceinline__ float ex2f(float x) {
    float y;
    asm("ex2.approx.ftz.f32 %0, %1;" : "=f"(y) : "f"(x));
    return y;
}

__device__ __forceinline__ uint32_t pack2h(float a, float b) {
    __half2 v(__float2half(a), __float2half(b));
    return *(uint32_t*)&v;
}
__device__ __forceinline__ uint32_t pack2h_lo(float a, float b) {
    __half ha = __float2half(a), hb = __float2half(b);
    __half2 v(__float2half(a - __half2float(ha)),
              __float2half(b - __half2float(hb)));
    return *(uint32_t*)&v;
}

// ---------------------------------------------------------------------------
// fp32 -> fp16 hi/lo split, and hi-only convert (for weights)
// ---------------------------------------------------------------------------
__global__ __launch_bounds__(256) void split_f16(const float* __restrict__ src,
                                                 __half* __restrict__ hi,
                                                 __half* __restrict__ lo,
                                                 int n) {
    int i = (blockIdx.x * blockDim.x + threadIdx.x) * 4;
    if (i >= n) return;
    float4 v = *(const float4*)(src + i);
    *(uint32_t*)(hi + i)     = pack2h(v.x, v.y);
    *(uint32_t*)(hi + i + 2) = pack2h(v.z, v.w);
    *(uint32_t*)(lo + i)     = pack2h_lo(v.x, v.y);
    *(uint32_t*)(lo + i + 2) = pack2h_lo(v.z, v.w);
}

__global__ __launch_bounds__(256) void conv_f16(const float* __restrict__ src,
                                                __half* __restrict__ hi, int n) {
    int i = (blockIdx.x * blockDim.x + threadIdx.x) * 4;
    if (i >= n) return;
    float4 v = *(const float4*)(src + i);
    *(uint32_t*)(hi + i)     = pack2h(v.x, v.y);
    *(uint32_t*)(hi + i + 2) = pack2h(v.z, v.w);
}

// ---------------------------------------------------------------------------
// fp16x2 HMMA GEMM (NT): C = (Ahi+Alo) * Bhi^T, fp32 accum.
// Round-9 proven configuration: 256 thr, 2x4 warp grid, 64x32 warp tile,
// interleaved hi/lo MMA order, 3-stage swizzled pipeline, one barrier/chunk.
// SPLIT epilogue writes lo only for columns < lo_cols (dead-store elim:
// flash reads qkv_lo only for Q columns, i.e. col < 1024).
// ---------------------------------------------------------------------------
#define KC 32
#define TILE2_B (128 * 64)          // 8192 B per tensor tile
#define STAGE2_B (3 * TILE2_B)      // 24576 B (Ah, Al, Bh)
#define GSMEM (3 * STAGE2_B)        // 73728 B, 3 stages

__device__ __forceinline__ uint32_t gsw(uint32_t row, uint32_t c4) {
    return row * 64u + ((c4 ^ (row & 3u)) << 4);
}

template <bool SPLIT>
__global__ __launch_bounds__(256) void gemm_hmma(
    const __half* __restrict__ Ahi, const __half* __restrict__ Alo,
    const __half* __restrict__ Bhi,
    float* __restrict__ C, __half* __restrict__ Chi,
    __half* __restrict__ Clo, int M, int N, int K, int lo_cols) {
    extern __shared__ char sm[];
    const uint32_t sbase = smem_u32_of(sm);

    const int tid  = threadIdx.x;
    const int wid  = tid >> 5;
    const int lane = tid & 31;
    const int m0 = blockIdx.y * 128;
    const int n0 = blockIdx.x * 128;
    const int wm = wid >> 2;
    const int wn = wid & 3;

    // Loader: thread -> (row = tid>>1, two 16B chunks)
    const int lrow = tid >> 1;
    const int lc0  = (tid & 1) * 2;
    const __half* gAh = Ahi + (size_t)(m0 + lrow) * K;
    const __half* gAl = Alo + (size_t)(m0 + lrow) * K;
    const __half* gBh = Bhi + (size_t)(n0 + lrow) * K;

    float acc[4][4][4] = {};
    const int NCH = K / KC;

    auto load_stage = [&](int c, int s) {
        const uint32_t st = sbase + (uint32_t)s * STAGE2_B;
        #pragma unroll
        for (int j = 0; j < 2; j++) {
            const uint32_t c4 = (uint32_t)(lc0 + j);
            const uint32_t dof = gsw((uint32_t)lrow, c4);
            const size_t go = (size_t)c * KC + c4 * 8;
            CPA16(st + dof,               gAh + go);
            CPA16(st + TILE2_B + dof,     gAl + go);
            CPA16(st + 2 * TILE2_B + dof, gBh + go);
        }
    };

    load_stage(0, 0);
    CPA_COMMIT();
    load_stage(1, 1);
    CPA_COMMIT();

    const int arow = wm * 64 + (lane & 15);
    const uint32_t ac4b = (uint32_t)(lane >> 4);
    const int brow = wn * 32 + (lane & 7) + ((lane >> 4) << 3);
    const uint32_t bc4b = (uint32_t)((lane >> 3) & 1);

    for (int c = 0; c < NCH; c++) {
        if (c + 1 < NCH) CPA_WAIT1(); else CPA_WAIT0();
        __syncthreads();
        if (c + 2 < NCH) {
            load_stage(c + 2, (c + 2) % 3);
            CPA_COMMIT();
        }

        const uint32_t Ah_b = sbase + (uint32_t)(c % 3) * STAGE2_B;
        const uint32_t Al_b = Ah_b + TILE2_B;
        const uint32_t Bh_b = Ah_b + 2 * TILE2_B;

        #pragma unroll
        for (int ks = 0; ks < 2; ks++) {
            const uint32_t ac4 = (uint32_t)(ks * 2) + ac4b;
            const uint32_t bc4 = (uint32_t)(ks * 2) + bc4b;
            uint32_t bh[2][4];
            #pragma unroll
            for (int nj2 = 0; nj2 < 2; nj2++)
                ldsm4(bh[nj2], Bh_b + gsw((uint32_t)(brow + nj2 * 16), bc4));
            uint32_t ah[4][4], al[4][4];
            #pragma unroll
            for (int mi = 0; mi < 4; mi++) {
                const uint32_t aoff = gsw((uint32_t)(arow + mi * 16), ac4);
                ldsm4(ah[mi], Ah_b + aoff);
                ldsm4(al[mi], Al_b + aoff);
            }
            #pragma unroll
            for (int nj2 = 0; nj2 < 2; nj2++) {
                #pragma unroll
                for (int mi = 0; mi < 4; mi++) {
                    #pragma unroll
                    for (int j = 0; j < 2; j++) {
                        float* a4 = acc[mi][nj2 * 2 + j];
                        mma_f16(a4, ah[mi], &bh[nj2][2 * j]);
                        mma_f16(a4, al[mi], &bh[nj2][2 * j]);
                    }
                }
            }
        }
    }

    const int gr = lane >> 2;
    const int gc = (lane & 3) * 2;
    const bool write_lo = SPLIT && (n0 < lo_cols);   // CTA-uniform
    #pragma unroll
    for (int mi = 0; mi < 4; mi++) {
        #pragma unroll
        for (int nj = 0; nj < 4; nj++) {
            const int row = m0 + wm * 64 + mi * 16 + gr;
            const int col = n0 + wn * 32 + nj * 8 + gc;
            if (SPLIT) {
                *(uint32_t*)&Chi[(size_t)row * N + col] = pack2h(acc[mi][nj][0], acc[mi][nj][1]);
                *(uint32_t*)&Chi[(size_t)(row + 8) * N + col] = pack2h(acc[mi][nj][2], acc[mi][nj][3]);
                if (write_lo) {
                    *(uint32_t*)&Clo[(size_t)row * N + col] = pack2h_lo(acc[mi][nj][0], acc[mi][nj][1]);
                    *(uint32_t*)&Clo[(size_t)(row + 8) * N + col] = pack2h_lo(acc[mi][nj][2], acc[mi][nj][3]);
                }
            } else {
                *(float2*)&C[(size_t)row * N + col] =
                    make_float2(acc[mi][nj][0], acc[mi][nj][1]);
                *(float2*)&C[(size_t)(row + 8) * N + col] =
                    make_float2(acc[mi][nj][2], acc[mi][nj][3]);
            }
        }
    }
}

// ---------------------------------------------------------------------------
// Tensor-core causal flash attention (fp16x2). Round-9 proven version.
// Q and P kept hi+lo (22-bit); K, V fp16-rounded. One CTA = 128-row q-tile,
// 8 warps, k-tiles of 64, double-buffered K/V, one __syncthreads per tile.
// ---------------------------------------------------------------------------
#define FA_STR 144                  // bytes per smem row (64 fp16 + 8 pad)
#define FA_QT  (128 * FA_STR)       // 18432 (Q tile: 128 rows)
#define FA_KT  (64 * FA_STR)        // 9216  (K/V tile: 64 rows)
#define FA_SMEM (2 * FA_QT + 2 * 2 * FA_KT)   // 73728

__global__ __launch_bounds__(256) void flash_tc(
    const __half* __restrict__ qkh, const __half* __restrict__ qkl,
    __half* __restrict__ oh, __half* __restrict__ ol) {
    extern __shared__ char sm[];
    const uint32_t sb = smem_u32_of(sm);
    const int qt = (int)gridDim.x - 1 - (int)blockIdx.x;   // long tiles first
    const int h  = blockIdx.y;
    const int b  = blockIdx.z;
    const int tid = threadIdx.x;
    const int w = tid >> 5;
    const int l = tid & 31;

    // Q load: 128 rows (hi + lo), thread -> (row = tid>>1, 64B half)
    {
        const int r  = tid >> 1;
        const int hf = tid & 1;
        const size_t qoff = ((size_t)(b * TT + qt * 128 + r)) * QKV_COLS + h * HD + hf * 32;
        const uint32_t d0 = sb + (uint32_t)r * FA_STR + (uint32_t)hf * 64;
        #pragma unroll
        for (int i = 0; i < 4; i++) {
            CPA16(d0 + 16 * i,         qkh + qoff + 8 * i);
            CPA16(d0 + FA_QT + 16 * i, qkl + qoff + 8 * i);
        }
    }

    // K/V load (hi only): 64 rows, thread -> (row = tid>>2, 32B quarter)
    const int kr = tid >> 2;
    const int kq = tid & 3;
    auto load_kv = [&](int kt, int s) {
        const size_t koff = ((size_t)(b * TT + kt * 64 + kr)) * QKV_COLS + HH + h * HD + kq * 16;
        const size_t voff = koff + HH;
        const uint32_t d = sb + 2 * FA_QT + (uint32_t)s * 2 * FA_KT
                         + (uint32_t)kr * FA_STR + (uint32_t)kq * 32;
        CPA16(d,              qkh + koff);
        CPA16(d + 16,         qkh + koff + 8);
        CPA16(d + FA_KT,      qkh + voff);
        CPA16(d + FA_KT + 16, qkh + voff + 8);
    };

    load_kv(0, 0);
    CPA_COMMIT();

    float o[8][4] = {};
    float m0 = -1e30f, m1 = -1e30f, l0 = 0.0f, l1 = 0.0f;
    uint32_t qfh[4][4], qfl[4][4];
    const int nkt = 2 * qt + 2;
    const float SCL = 0.18033688011112042f;    // (1/8) * log2(e)

    const uint32_t qa = sb + (uint32_t)(w * 16 + (l & 15)) * FA_STR + (uint32_t)((l >> 4) * 8) * 2;
    const uint32_t kb_row = (uint32_t)((l & 7) + ((l >> 4) << 3)) * FA_STR
                          + (uint32_t)(((l >> 3) & 1) * 8) * 2;
    const uint32_t vb_row = (uint32_t)((l & 7) + (((l >> 3) & 1) << 3)) * FA_STR
                          + (uint32_t)((l >> 4) * 8) * 2;

    const int grow0 = qt * 128 + w * 16 + (l >> 2);   // global q row (first)
    const int cb    = (l & 3) * 2;

    for (int kt = 0; kt < nkt; kt++) {
        const int s = kt & 1;
        CPA_WAIT0();
        __syncthreads();
        if (kt + 1 < nkt) {
            load_kv(kt + 1, s ^ 1);
            CPA_COMMIT();
        }

        if (kt == 0) {
            #pragma unroll
            for (int ks = 0; ks < 4; ks++) {
                ldsm4(qfh[ks], qa + ks * 32);
                ldsm4(qfl[ks], qa + FA_QT + ks * 32);
            }
        }

        const uint32_t Kb = sb + 2 * FA_QT + (uint32_t)s * 2 * FA_KT;
        const uint32_t Vb = Kb + FA_KT;

        // S = (Qhi+Qlo) Kh^T (fp16x2)
        float sc[8][4] = {};
        #pragma unroll
        for (int g = 0; g < 4; g++) {
            #pragma unroll
            for (int ks = 0; ks < 4; ks++) {
                uint32_t bh[4];
                ldsm4(bh, Kb + (uint32_t)(g * 16) * FA_STR + kb_row + ks * 32);
                mma_f16(sc[2 * g],     qfh[ks], &bh[0]);
                mma_f16(sc[2 * g],     qfl[ks], &bh[0]);
                mma_f16(sc[2 * g + 1], qfh[ks], &bh[2]);
                mma_f16(sc[2 * g + 1], qfl[ks], &bh[2]);
            }
        }

        // scale + causal mask (tiles at/after the diagonal band)
        const bool diag = (kt >= 2 * qt);
        float mx0 = -1e30f, mx1 = -1e30f;
        #pragma unroll
        for (int j = 0; j < 8; j++) {
            float s0 = sc[j][0] * SCL, s1 = sc[j][1] * SCL;
            float s2 = sc[j][2] * SCL, s3 = sc[j][3] * SCL;
            if (diag) {
                const int c = kt * 64 + j * 8 + cb;
                if (c     > grow0)     s0 = -1e30f;
                if (c + 1 > grow0)     s1 = -1e30f;
                if (c     > grow0 + 8) s2 = -1e30f;
                if (c + 1 > grow0 + 8) s3 = -1e30f;
            }
            sc[j][0] = s0; sc[j][1] = s1; sc[j][2] = s2; sc[j][3] = s3;
            mx0 = fmaxf(mx0, fmaxf(s0, s1));
            mx1 = fmaxf(mx1, fmaxf(s2, s3));
        }
        mx0 = fmaxf(mx0, __shfl_xor_sync(0xffffffffu, mx0, 1));
        mx0 = fmaxf(mx0, __shfl_xor_sync(0xffffffffu, mx0, 2));
        mx1 = fmaxf(mx1, __shfl_xor_sync(0xffffffffu, mx1, 1));
        mx1 = fmaxf(mx1, __shfl_xor_sync(0xffffffffu, mx1, 2));

        const float mn0 = fmaxf(m0, mx0);
        const float mn1 = fmaxf(m1, mx1);
        const float corr0 = ex2f(m0 - mn0);
        const float corr1 = ex2f(m1 - mn1);
        float sum0 = 0.0f, sum1 = 0.0f;
        #pragma unroll
        for (int j = 0; j < 8; j++) {
            sc[j][0] = ex2f(sc[j][0] - mn0); sum0 += sc[j][0];
            sc[j][1] = ex2f(sc[j][1] - mn0); sum0 += sc[j][1];
            sc[j][2] = ex2f(sc[j][2] - mn1); sum1 += sc[j][2];
            sc[j][3] = ex2f(sc[j][3] - mn1); sum1 += sc[j][3];
        }
        sum0 += __shfl_xor_sync(0xffffffffu, sum0, 1);
        sum0 += __shfl_xor_sync(0xffffffffu, sum0, 2);
        sum1 += __shfl_xor_sync(0xffffffffu, sum1, 1);
        sum1 += __shfl_xor_sync(0xffffffffu, sum1, 2);
        l0 = l0 * corr0 + sum0;
        l1 = l1 * corr1 + sum1;
        m0 = mn0; m1 = mn1;

        #pragma unroll
        for (int j = 0; j < 8; j++) {
            o[j][0] *= corr0; o[j][1] *= corr0;
            o[j][2] *= corr1; o[j][3] *= corr1;
        }

        // P fragments (hi/lo fp16) from S accumulators
        uint32_t pah[4][4], pal[4][4];
        #pragma unroll
        for (int ks = 0; ks < 4; ks++) {
            pah[ks][0] = pack2h(sc[2 * ks][0],        sc[2 * ks][1]);
            pal[ks][0] = pack2h_lo(sc[2 * ks][0],     sc[2 * ks][1]);
            pah[ks][1] = pack2h(sc[2 * ks][2],        sc[2 * ks][3]);
            pal[ks][1] = pack2h_lo(sc[2 * ks][2],     sc[2 * ks][3]);
            pah[ks][2] = pack2h(sc[2 * ks + 1][0],    sc[2 * ks + 1][1]);
            pal[ks][2] = pack2h_lo(sc[2 * ks + 1][0], sc[2 * ks + 1][1]);
            pah[ks][3] = pack2h(sc[2 * ks + 1][2],    sc[2 * ks + 1][3]);
            pal[ks][3] = pack2h_lo(sc[2 * ks + 1][2], sc[2 * ks + 1][3]);
        }

        // O += (Phi+Plo) Vh (fp16x2), V via ldmatrix.trans
        #pragma unroll
        for (int g = 0; g < 4; g++) {
            #pragma unroll
            for (int ks = 0; ks < 4; ks++) {
                uint32_t vh[4];
                ldsm4t(vh, Vb + (uint32_t)(ks * 16) * FA_STR + vb_row + g * 32);
                mma_f16(o[2 * g],     pah[ks], &vh[0]);
                mma_f16(o[2 * g],     pal[ks], &vh[0]);
                mma_f16(o[2 * g + 1], pah[ks], &vh[2]);
                mma_f16(o[2 * g + 1], pal[ks], &vh[2]);
            }
        }
    }

    // Epilogue: normalize + write hi/lo fp16
    const float i0 = 1.0f / l0;
    const float i1 = 1.0f / l1;
    const size_t row0 = (size_t)(b * TT + qt * 128 + w * 16 + (l >> 2));
    const size_t row1 = row0 + 8;
    const int colb = h * HD + cb;
    #pragma unroll
    for (int j = 0; j < 8; j++) {
        const size_t c = colb + j * 8;
        const float v0 = o[j][0] * i0, v1 = o[j][1] * i0;
        const float v2 = o[j][2] * i1, v3 = o[j][3] * i1;
        *(uint32_t*)&oh[row0 * HH + c] = pack2h(v0, v1);
        *(uint32_t*)&ol[row0 * HH + c] = pack2h_lo(v0, v1);
        *(uint32_t*)&oh[row1 * HH + c] = pack2h(v2, v3);
        *(uint32_t*)&ol[row1 * HH + c] = pack2h_lo(v2, v3);
    }
}

// ---------------------------------------------------------------------------
extern "C" void kernel_launch(void* const* d_in, const int* in_sizes, int n_in,
                              void* d_out, int out_size) {
    const float* x    = (const float*)d_in[0];   // [4,2048,1024]
    const float* Wqkv = (const float*)d_in[1];   // [3072,1024]
    const float* Wout = (const float*)d_in[2];   // [1024,1024]
    float* out = (float*)d_out;                  // [4,2048,1024]

    __half *qh, *ql, *xhi, *xlo, *wqh, *woh, *ahi, *alo;
    cudaGetSymbolAddress((void**)&qh,  g_qkv_hi);
    cudaGetSymbolAddress((void**)&ql,  g_qkv_lo);
    cudaGetSymbolAddress((void**)&xhi, g_x_hi);
    cudaGetSymbolAddress((void**)&xlo, g_x_lo);
    cudaGetSymbolAddress((void**)&wqh, g_wqkv_hi);
    cudaGetSymbolAddress((void**)&woh, g_wout_hi);
    cudaGetSymbolAddress((void**)&ahi, g_attn_hi);
    cudaGetSymbolAddress((void**)&alo, g_attn_lo);

    cudaFuncSetAttribute(gemm_hmma<true>,  cudaFuncAttributeMaxDynamicSharedMemorySize, GSMEM);
    cudaFuncSetAttribute(gemm_hmma<false>, cudaFuncAttributeMaxDynamicSharedMemorySize, GSMEM);
    cudaFuncSetAttribute(flash_tc, cudaFuncAttributeMaxDynamicSharedMemorySize, FA_SMEM);

    // Splits/converts
    {
        int n1 = ROWS * HH;
        split_f16<<<(n1 / 4 + 255) / 256, 256>>>(x, xhi, xlo, n1);
        int n2 = QKV_COLS * HH;
        conv_f16<<<(n2 / 4 + 255) / 256, 256>>>(Wqkv, wqh, n2);
        int n3 = HH * HH;
        conv_f16<<<(n3 / 4 + 255) / 256, 256>>>(Wout, woh, n3);
    }

    // 1) qkv = x @ W_qkv^T -> fp16 hi always, lo only for Q columns (<1024)
    gemm_hmma<true><<<dim3(QKV_COLS / 128, ROWS / 128), 256, GSMEM>>>(
        xhi, xlo, wqh, nullptr, qh, ql, ROWS, QKV_COLS, HH, HH);

    // 2) tensor-core causal flash attention (128-row q-tiles) -> fp16 hi/lo
    flash_tc<<<dim3(TT / 128, NH, BB), 256, FA_SMEM>>>(qh, ql, ahi, alo);

    // 3) out = attn @ W_out^T -> fp32
    gemm_hmma<false><<<dim3(HH / 128, ROWS / 128), 256, GSMEM>>>(
        ahi, alo, woh, out, nullptr, nullptr, ROWS, HH, HH, 0);
}